// round 2
// baseline (speedup 1.0000x reference)
#include <cuda_runtime.h>
#include <cuda_bf16.h>
#include <cstdint>

// Problem constants (match reference)
#define N_USERS 200000
#define N_ITEMS 400000
#define N_NODES (N_USERS + N_ITEMS)   // 600000
#define EMB_DIM 128
#define N_EDGES 3000000
#define VEC4_PER_ROW (EMB_DIM / 4)    // 32
#define TOTAL_F ((size_t)N_NODES * EMB_DIM)          // 76.8M floats
#define TOTAL_V4 (TOTAL_F / 4)                       // 19.2M float4

// Static scratch (allowed: __device__ globals, no runtime alloc)
__device__ float g_bufA[TOTAL_F];
__device__ float g_bufB[TOTAL_F];

// ---------------------------------------------------------------------------
// Init: x = concat(emb_user, emb_item); out = 0.25*x; y(=B) = 0
// ---------------------------------------------------------------------------
__global__ void init_kernel(const float4* __restrict__ user,
                            const float4* __restrict__ item,
                            float4* __restrict__ out,
                            float4* __restrict__ x,
                            float4* __restrict__ y) {
    size_t i = (size_t)blockIdx.x * blockDim.x + threadIdx.x;
    if (i >= TOTAL_V4) return;
    const size_t user_v4 = (size_t)N_USERS * VEC4_PER_ROW;
    float4 v = (i < user_v4) ? user[i] : item[i - user_v4];
    x[i] = v;
    y[i] = make_float4(0.f, 0.f, 0.f, 0.f);
    out[i] = make_float4(0.25f * v.x, 0.25f * v.y, 0.25f * v.z, 0.25f * v.w);
}

// ---------------------------------------------------------------------------
// Scatter: one warp per edge. y[row] += val * x[col]  (vector red, v4.f32)
// Indices are int32 (JAX default config downgrades int64 -> int32).
// Bounds guard is a diagnostic hedge: skips malformed edges instead of IMA.
// ---------------------------------------------------------------------------
__global__ void scatter_kernel(const int* __restrict__ rows,
                               const int* __restrict__ cols,
                               const float* __restrict__ vals,
                               const float* __restrict__ x,
                               float* __restrict__ y) {
    int warp_in_block = threadIdx.x >> 5;
    int lane = threadIdx.x & 31;
    long long e = (long long)blockIdx.x * (blockDim.x >> 5) + warp_in_block;
    if (e >= N_EDGES) return;

    int r = __ldg(rows + e);
    int c = __ldg(cols + e);
    float v = __ldg(vals + e);
    if ((unsigned)r >= (unsigned)N_NODES || (unsigned)c >= (unsigned)N_NODES) return;

    const float4* xr = reinterpret_cast<const float4*>(x + (size_t)c * EMB_DIM);
    float4 m = __ldg(xr + lane);
    m.x *= v; m.y *= v; m.z *= v; m.w *= v;

    float* dst = y + (size_t)r * EMB_DIM + lane * 4;
    asm volatile("red.global.add.v4.f32 [%0], {%1, %2, %3, %4};"
                 :: "l"(dst), "f"(m.x), "f"(m.y), "f"(m.z), "f"(m.w)
                 : "memory");
}

// ---------------------------------------------------------------------------
// Post: out += 0.25*y ; optionally zero the old x buffer (becomes next y)
// ---------------------------------------------------------------------------
__global__ void post_kernel(float4* __restrict__ out,
                            const float4* __restrict__ y,
                            float4* __restrict__ zero_me) {
    size_t i = (size_t)blockIdx.x * blockDim.x + threadIdx.x;
    if (i >= TOTAL_V4) return;
    float4 a = y[i];
    float4 o = out[i];
    o.x += 0.25f * a.x; o.y += 0.25f * a.y;
    o.z += 0.25f * a.z; o.w += 0.25f * a.w;
    out[i] = o;
    if (zero_me) zero_me[i] = make_float4(0.f, 0.f, 0.f, 0.f);
}

extern "C" void kernel_launch(void* const* d_in, const int* in_sizes, int n_in,
                              void* d_out, int out_size) {
    const float* emb_user = (const float*)d_in[0];
    const float* emb_item = (const float*)d_in[1];
    const int* edge_row = (const int*)d_in[2];
    const int* edge_col = (const int*)d_in[3];
    const float* edge_val = (const float*)d_in[4];
    float* out = (float*)d_out;

    float* A;
    float* B;
    cudaGetSymbolAddress((void**)&A, g_bufA);
    cudaGetSymbolAddress((void**)&B, g_bufB);

    const int T = 256;
    const int gridElem = (int)((TOTAL_V4 + T - 1) / T);
    const int warpsPerBlock = T / 32;
    const int gridEdge = (N_EDGES + warpsPerBlock - 1) / warpsPerBlock;

    // x = A = concat(embs); out = 0.25*x; B = 0
    init_kernel<<<gridElem, T>>>((const float4*)emb_user, (const float4*)emb_item,
                                 (float4*)out, (float4*)A, (float4*)B);

    // Layer 1: A -> B ; out += 0.25*B ; zero A
    scatter_kernel<<<gridEdge, T>>>(edge_row, edge_col, edge_val, A, B);
    post_kernel<<<gridElem, T>>>((float4*)out, (const float4*)B, (float4*)A);

    // Layer 2: B -> A ; out += 0.25*A ; zero B
    scatter_kernel<<<gridEdge, T>>>(edge_row, edge_col, edge_val, B, A);
    post_kernel<<<gridElem, T>>>((float4*)out, (const float4*)A, (float4*)B);

    // Layer 3: A -> B ; out += 0.25*B
    scatter_kernel<<<gridEdge, T>>>(edge_row, edge_col, edge_val, A, B);
    post_kernel<<<gridElem, T>>>((float4*)out, (const float4*)B, nullptr);
}

// round 3
// speedup vs baseline: 2.3241x; 2.3241x over previous
#include <cuda_runtime.h>
#include <cuda_bf16.h>
#include <cstdint>

// Problem constants (match reference)
#define N_USERS 200000
#define N_ITEMS 400000
#define N_NODES (N_USERS + N_ITEMS)   // 600000
#define EMB_DIM 128
#define N_EDGES 3000000
#define VEC4_PER_ROW (EMB_DIM / 4)    // 32
#define TOTAL_F ((size_t)N_NODES * EMB_DIM)   // 76.8M floats

#define SCAN_BLOCK 1024
#define N_SCAN_BLOCKS ((N_NODES + SCAN_BLOCK - 1) / SCAN_BLOCK)  // 586

// Static scratch (allowed: __device__ globals; zero-initialized at load)
__device__ float g_bufA[TOTAL_F];
__device__ float g_bufB[TOTAL_F];
__device__ int   g_count[N_NODES];
__device__ int   g_offset[N_NODES];
__device__ int   g_pos[N_NODES];
__device__ int   g_bsum[SCAN_BLOCK];      // >= N_SCAN_BLOCKS
__device__ int   g_pcol[N_EDGES];
__device__ float g_pval[N_EDGES];

// ---------------------------------------------------------------------------
// CSR build
// ---------------------------------------------------------------------------
__global__ void zero_counts_kernel(int* __restrict__ count) {
    int i = blockIdx.x * blockDim.x + threadIdx.x;
    if (i < N_NODES) count[i] = 0;
}

__global__ void histogram_kernel(const int* __restrict__ rows,
                                 int* __restrict__ count) {
    int e = blockIdx.x * blockDim.x + threadIdx.x;
    if (e < N_EDGES) atomicAdd(&count[rows[e]], 1);
}

// Block-level exclusive scan (Hillis-Steele inclusive, then subtract own)
__global__ void scan1_kernel(const int* __restrict__ count,
                             int* __restrict__ offset,
                             int* __restrict__ bsum) {
    __shared__ int sh[SCAN_BLOCK];
    int i = blockIdx.x * SCAN_BLOCK + threadIdx.x;
    int v = (i < N_NODES) ? count[i] : 0;
    sh[threadIdx.x] = v;
    __syncthreads();
    #pragma unroll
    for (int d = 1; d < SCAN_BLOCK; d <<= 1) {
        int t = (threadIdx.x >= d) ? sh[threadIdx.x - d] : 0;
        __syncthreads();
        sh[threadIdx.x] += t;
        __syncthreads();
    }
    if (i < N_NODES) offset[i] = sh[threadIdx.x] - v;
    if (threadIdx.x == SCAN_BLOCK - 1) bsum[blockIdx.x] = sh[SCAN_BLOCK - 1];
}

__global__ void scan2_kernel(int* __restrict__ bsum, int nb) {
    __shared__ int sh[SCAN_BLOCK];
    int v = (threadIdx.x < nb) ? bsum[threadIdx.x] : 0;
    sh[threadIdx.x] = v;
    __syncthreads();
    #pragma unroll
    for (int d = 1; d < SCAN_BLOCK; d <<= 1) {
        int t = (threadIdx.x >= d) ? sh[threadIdx.x - d] : 0;
        __syncthreads();
        sh[threadIdx.x] += t;
        __syncthreads();
    }
    if (threadIdx.x < nb) bsum[threadIdx.x] = sh[threadIdx.x] - v;  // exclusive
}

__global__ void scan3_kernel(int* __restrict__ offset,
                             const int* __restrict__ bsum,
                             int* __restrict__ pos) {
    int i = blockIdx.x * SCAN_BLOCK + threadIdx.x;
    if (i < N_NODES) {
        int o = offset[i] + bsum[blockIdx.x];
        offset[i] = o;
        pos[i] = o;
    }
}

__global__ void permute_kernel(const int* __restrict__ rows,
                               const int* __restrict__ cols,
                               const float* __restrict__ vals,
                               int* __restrict__ pos,
                               int* __restrict__ pcol,
                               float* __restrict__ pval) {
    int e = blockIdx.x * blockDim.x + threadIdx.x;
    if (e >= N_EDGES) return;
    int r = rows[e];
    int p = atomicAdd(&pos[r], 1);
    pcol[p] = cols[e];
    pval[p] = vals[e];
}

// ---------------------------------------------------------------------------
// Pull-style SpMM: one warp per output row. No atomics, full-row overwrite.
// SPLIT = gather source is split (user|item) inputs; FUSED = layer-3 epilogue.
// ---------------------------------------------------------------------------
template <bool SPLIT, bool FUSED>
__global__ void spmm_kernel(const int* __restrict__ offset,
                            const int* __restrict__ count,
                            const int* __restrict__ pcol,
                            const float* __restrict__ pval,
                            const float4* __restrict__ u,    // user embs (v4)
                            const float4* __restrict__ it,   // item embs (v4)
                            const float4* __restrict__ x,    // gather src (!SPLIT)
                            float4* __restrict__ dst,        // layer output
                            const float4* __restrict__ accA, // FUSED: layer-1 out
                            const float4* __restrict__ accB, // FUSED: layer-2 out
                            float4* __restrict__ out) {      // FUSED: final out
    int lane = threadIdx.x & 31;
    int r = (blockIdx.x * blockDim.x + threadIdx.x) >> 5;
    if (r >= N_NODES) return;

    int start = __ldg(offset + r);
    int deg = __ldg(count + r);

    float4 acc = make_float4(0.f, 0.f, 0.f, 0.f);
    for (int j = start; j < start + deg; ++j) {
        int c = __ldg(pcol + j);
        float v = __ldg(pval + j);
        const float4* base;
        if (SPLIT)
            base = (c < N_USERS) ? (u + (size_t)c * VEC4_PER_ROW)
                                 : (it + (size_t)(c - N_USERS) * VEC4_PER_ROW);
        else
            base = x + (size_t)c * VEC4_PER_ROW;
        float4 m = __ldg(base + lane);
        acc.x += v * m.x; acc.y += v * m.y;
        acc.z += v * m.z; acc.w += v * m.w;
    }

    size_t idx = (size_t)r * VEC4_PER_ROW + lane;
    if (FUSED) {
        float4 x0 = (r < N_USERS)
                        ? __ldg(u + (size_t)r * VEC4_PER_ROW + lane)
                        : __ldg(it + (size_t)(r - N_USERS) * VEC4_PER_ROW + lane);
        float4 a = __ldg(accA + idx);
        float4 b = __ldg(accB + idx);
        float4 o;
        o.x = 0.25f * (x0.x + a.x + b.x + acc.x);
        o.y = 0.25f * (x0.y + a.y + b.y + acc.y);
        o.z = 0.25f * (x0.z + a.z + b.z + acc.z);
        o.w = 0.25f * (x0.w + a.w + b.w + acc.w);
        out[idx] = o;
    } else {
        dst[idx] = acc;
    }
}

extern "C" void kernel_launch(void* const* d_in, const int* in_sizes, int n_in,
                              void* d_out, int out_size) {
    const float4* emb_user = (const float4*)d_in[0];
    const float4* emb_item = (const float4*)d_in[1];
    const int* edge_row = (const int*)d_in[2];
    const int* edge_col = (const int*)d_in[3];
    const float* edge_val = (const float*)d_in[4];
    float4* out = (float4*)d_out;

    float *A_, *B_;
    int *count_, *offset_, *pos_, *bsum_, *pcol_;
    float *pval_;
    cudaGetSymbolAddress((void**)&A_, g_bufA);
    cudaGetSymbolAddress((void**)&B_, g_bufB);
    cudaGetSymbolAddress((void**)&count_, g_count);
    cudaGetSymbolAddress((void**)&offset_, g_offset);
    cudaGetSymbolAddress((void**)&pos_, g_pos);
    cudaGetSymbolAddress((void**)&bsum_, g_bsum);
    cudaGetSymbolAddress((void**)&pcol_, g_pcol);
    cudaGetSymbolAddress((void**)&pval_, g_pval);
    float4* A = (float4*)A_;
    float4* B = (float4*)B_;

    const int T = 256;
    const int gridNode = (N_NODES + T - 1) / T;
    const int gridEdge = (N_EDGES + T - 1) / T;
    const int warpsPerBlock = T / 32;
    const int gridRow = (N_NODES + warpsPerBlock - 1) / warpsPerBlock;

    // ---- CSR build (edges identical across layers: build once) ----
    zero_counts_kernel<<<gridNode, T>>>(count_);
    histogram_kernel<<<gridEdge, T>>>(edge_row, count_);
    scan1_kernel<<<N_SCAN_BLOCKS, SCAN_BLOCK>>>(count_, offset_, bsum_);
    scan2_kernel<<<1, SCAN_BLOCK>>>(bsum_, N_SCAN_BLOCKS);
    scan3_kernel<<<N_SCAN_BLOCKS, SCAN_BLOCK>>>(offset_, bsum_, pos_);
    permute_kernel<<<gridEdge, T>>>(edge_row, edge_col, edge_val,
                                    pos_, pcol_, pval_);

    // ---- Layer 1: gather split inputs -> A ----
    spmm_kernel<true, false><<<gridRow, T>>>(offset_, count_, pcol_, pval_,
                                             emb_user, emb_item, nullptr,
                                             A, nullptr, nullptr, nullptr);
    // ---- Layer 2: gather A -> B ----
    spmm_kernel<false, false><<<gridRow, T>>>(offset_, count_, pcol_, pval_,
                                              emb_user, emb_item, A,
                                              B, nullptr, nullptr, nullptr);
    // ---- Layer 3 fused: gather B, epilogue out = 0.25*(x0 + A + B + y) ----
    spmm_kernel<false, true><<<gridRow, T>>>(offset_, count_, pcol_, pval_,
                                             emb_user, emb_item, B,
                                             nullptr, A, B, out);
}

// round 4
// speedup vs baseline: 2.5751x; 1.1080x over previous
#include <cuda_runtime.h>
#include <cuda_bf16.h>
#include <cstdint>

// Problem constants (match reference)
#define N_USERS 200000
#define N_ITEMS 400000
#define N_NODES (N_USERS + N_ITEMS)   // 600000
#define EMB_DIM 128
#define N_EDGES 3000000
#define VEC4_PER_ROW (EMB_DIM / 4)    // 32
#define TOTAL_F ((size_t)N_NODES * EMB_DIM)   // 76.8M floats

#define SCAN_BLOCK 1024
#define N_SCAN_BLOCKS ((N_NODES + SCAN_BLOCK - 1) / SCAN_BLOCK)  // 586

// Static scratch (allowed: __device__ globals)
__device__ float g_bufA[TOTAL_F];
__device__ float g_bufB[TOTAL_F];
__device__ int   g_count[N_NODES];
__device__ int   g_offset[N_NODES + 1];
__device__ int   g_pos[N_NODES];
__device__ int   g_bsum[SCAN_BLOCK];      // >= N_SCAN_BLOCKS
__device__ int2  g_pair[N_EDGES];         // (col, val-as-int) packed

// ---------------------------------------------------------------------------
// CSR build
// ---------------------------------------------------------------------------
__global__ void histogram_kernel(const int* __restrict__ rows,
                                 int* __restrict__ count) {
    int e = blockIdx.x * blockDim.x + threadIdx.x;
    if (e < N_EDGES) atomicAdd(&count[rows[e]], 1);
}

__global__ void scan1_kernel(const int* __restrict__ count,
                             int* __restrict__ offset,
                             int* __restrict__ bsum) {
    __shared__ int sh[SCAN_BLOCK];
    int i = blockIdx.x * SCAN_BLOCK + threadIdx.x;
    int v = (i < N_NODES) ? count[i] : 0;
    sh[threadIdx.x] = v;
    __syncthreads();
    #pragma unroll
    for (int d = 1; d < SCAN_BLOCK; d <<= 1) {
        int t = (threadIdx.x >= d) ? sh[threadIdx.x - d] : 0;
        __syncthreads();
        sh[threadIdx.x] += t;
        __syncthreads();
    }
    if (i < N_NODES) offset[i] = sh[threadIdx.x] - v;   // exclusive
    if (threadIdx.x == SCAN_BLOCK - 1) bsum[blockIdx.x] = sh[SCAN_BLOCK - 1];
}

__global__ void scan2_kernel(int* __restrict__ bsum, int nb) {
    __shared__ int sh[SCAN_BLOCK];
    int v = (threadIdx.x < nb) ? bsum[threadIdx.x] : 0;
    sh[threadIdx.x] = v;
    __syncthreads();
    #pragma unroll
    for (int d = 1; d < SCAN_BLOCK; d <<= 1) {
        int t = (threadIdx.x >= d) ? sh[threadIdx.x - d] : 0;
        __syncthreads();
        sh[threadIdx.x] += t;
        __syncthreads();
    }
    if (threadIdx.x < nb) bsum[threadIdx.x] = sh[threadIdx.x] - v;  // exclusive
}

__global__ void scan3_kernel(int* __restrict__ offset,
                             const int* __restrict__ bsum,
                             int* __restrict__ pos) {
    int i = blockIdx.x * SCAN_BLOCK + threadIdx.x;
    if (i < N_NODES) {
        int o = offset[i] + bsum[blockIdx.x];
        offset[i] = o;
        pos[i] = o;
        if (i == N_NODES - 1) offset[N_NODES] = N_EDGES;
    }
}

__global__ void permute_kernel(const int* __restrict__ rows,
                               const int* __restrict__ cols,
                               const float* __restrict__ vals,
                               int* __restrict__ pos,
                               int2* __restrict__ pair) {
    int e = blockIdx.x * blockDim.x + threadIdx.x;
    if (e >= N_EDGES) return;
    int r = rows[e];
    int p = atomicAdd(&pos[r], 1);
    int2 pr;
    pr.x = cols[e];
    pr.y = __float_as_int(vals[e]);
    pair[p] = pr;
}

// ---------------------------------------------------------------------------
// Pull-style SpMM: one warp per output row, no atomics.
// Unroll x2 with dual accumulators; packed (col,val) single LDG.64 broadcast.
// ---------------------------------------------------------------------------
template <bool SPLIT, bool FUSED>
__global__ void __launch_bounds__(512)
spmm_kernel(const int* __restrict__ offset,
            const int2* __restrict__ pair,
            const float4* __restrict__ u,    // user embs (v4)
            const float4* __restrict__ it,   // item embs (v4)
            const float4* __restrict__ x,    // gather src (!SPLIT)
            float4* __restrict__ dst,        // layer output
            const float4* __restrict__ accA, // FUSED: layer-1 out
            const float4* __restrict__ accB, // FUSED: layer-2 out
            float4* __restrict__ out) {      // FUSED: final out
    int lane = threadIdx.x & 31;
    int r = (blockIdx.x * blockDim.x + threadIdx.x) >> 5;
    if (r >= N_NODES) return;

    int j = __ldg(offset + r);
    int end = __ldg(offset + r + 1);

    float4 acc0 = make_float4(0.f, 0.f, 0.f, 0.f);
    float4 acc1 = make_float4(0.f, 0.f, 0.f, 0.f);

    #pragma unroll 1
    for (; j + 2 <= end; j += 2) {
        int2 e0 = __ldg(pair + j);
        int2 e1 = __ldg(pair + j + 1);
        const float4* b0;
        const float4* b1;
        if (SPLIT) {
            b0 = (e0.x < N_USERS) ? (u + (size_t)e0.x * VEC4_PER_ROW)
                                  : (it + (size_t)(e0.x - N_USERS) * VEC4_PER_ROW);
            b1 = (e1.x < N_USERS) ? (u + (size_t)e1.x * VEC4_PER_ROW)
                                  : (it + (size_t)(e1.x - N_USERS) * VEC4_PER_ROW);
        } else {
            b0 = x + (size_t)e0.x * VEC4_PER_ROW;
            b1 = x + (size_t)e1.x * VEC4_PER_ROW;
        }
        float4 m0 = __ldg(b0 + lane);
        float4 m1 = __ldg(b1 + lane);
        float v0 = __int_as_float(e0.y);
        float v1 = __int_as_float(e1.y);
        acc0.x += v0 * m0.x; acc0.y += v0 * m0.y;
        acc0.z += v0 * m0.z; acc0.w += v0 * m0.w;
        acc1.x += v1 * m1.x; acc1.y += v1 * m1.y;
        acc1.z += v1 * m1.z; acc1.w += v1 * m1.w;
    }
    if (j < end) {
        int2 e0 = __ldg(pair + j);
        const float4* b0;
        if (SPLIT)
            b0 = (e0.x < N_USERS) ? (u + (size_t)e0.x * VEC4_PER_ROW)
                                  : (it + (size_t)(e0.x - N_USERS) * VEC4_PER_ROW);
        else
            b0 = x + (size_t)e0.x * VEC4_PER_ROW;
        float4 m0 = __ldg(b0 + lane);
        float v0 = __int_as_float(e0.y);
        acc0.x += v0 * m0.x; acc0.y += v0 * m0.y;
        acc0.z += v0 * m0.z; acc0.w += v0 * m0.w;
    }

    float4 acc;
    acc.x = acc0.x + acc1.x; acc.y = acc0.y + acc1.y;
    acc.z = acc0.z + acc1.z; acc.w = acc0.w + acc1.w;

    size_t idx = (size_t)r * VEC4_PER_ROW + lane;
    if (FUSED) {
        float4 x0 = (r < N_USERS)
                        ? __ldg(u + (size_t)r * VEC4_PER_ROW + lane)
                        : __ldg(it + (size_t)(r - N_USERS) * VEC4_PER_ROW + lane);
        float4 a = __ldg(accA + idx);
        float4 b = __ldg(accB + idx);
        float4 o;
        o.x = 0.25f * (x0.x + a.x + b.x + acc.x);
        o.y = 0.25f * (x0.y + a.y + b.y + acc.y);
        o.z = 0.25f * (x0.z + a.z + b.z + acc.z);
        o.w = 0.25f * (x0.w + a.w + b.w + acc.w);
        out[idx] = o;
    } else {
        dst[idx] = acc;
    }
}

extern "C" void kernel_launch(void* const* d_in, const int* in_sizes, int n_in,
                              void* d_out, int out_size) {
    const float4* emb_user = (const float4*)d_in[0];
    const float4* emb_item = (const float4*)d_in[1];
    const int* edge_row = (const int*)d_in[2];
    const int* edge_col = (const int*)d_in[3];
    const float* edge_val = (const float*)d_in[4];
    float4* out = (float4*)d_out;

    float *A_, *B_;
    int *count_, *offset_, *pos_, *bsum_;
    int2 *pair_;
    cudaGetSymbolAddress((void**)&A_, g_bufA);
    cudaGetSymbolAddress((void**)&B_, g_bufB);
    cudaGetSymbolAddress((void**)&count_, g_count);
    cudaGetSymbolAddress((void**)&offset_, g_offset);
    cudaGetSymbolAddress((void**)&pos_, g_pos);
    cudaGetSymbolAddress((void**)&bsum_, g_bsum);
    cudaGetSymbolAddress((void**)&pair_, g_pair);
    float4* A = (float4*)A_;
    float4* B = (float4*)B_;

    const int T = 256;
    const int gridEdge = (N_EDGES + T - 1) / T;
    const int TS = 512;
    const int gridRow = (int)(((size_t)N_NODES * 32 + TS - 1) / TS);

    // ---- CSR build (edges identical across layers: build once) ----
    cudaMemsetAsync(count_, 0, N_NODES * sizeof(int));
    histogram_kernel<<<gridEdge, T>>>(edge_row, count_);
    scan1_kernel<<<N_SCAN_BLOCKS, SCAN_BLOCK>>>(count_, offset_, bsum_);
    scan2_kernel<<<1, SCAN_BLOCK>>>(bsum_, N_SCAN_BLOCKS);
    scan3_kernel<<<N_SCAN_BLOCKS, SCAN_BLOCK>>>(offset_, bsum_, pos_);
    permute_kernel<<<gridEdge, T>>>(edge_row, edge_col, edge_val, pos_, pair_);

    // ---- Layer 1: gather split inputs -> A ----
    spmm_kernel<true, false><<<gridRow, TS>>>(offset_, pair_,
                                              emb_user, emb_item, nullptr,
                                              A, nullptr, nullptr, nullptr);
    // ---- Layer 2: gather A -> B ----
    spmm_kernel<false, false><<<gridRow, TS>>>(offset_, pair_,
                                               emb_user, emb_item, A,
                                               B, nullptr, nullptr, nullptr);
    // ---- Layer 3 fused: gather B, epilogue out = 0.25*(x0 + A + B + y) ----
    spmm_kernel<false, true><<<gridRow, TS>>>(offset_, pair_,
                                              emb_user, emb_item, B,
                                              nullptr, A, B, out);
}

// round 5
// speedup vs baseline: 3.0331x; 1.1778x over previous
#include <cuda_runtime.h>
#include <cuda_fp16.h>
#include <cstdint>

// Problem constants (match reference)
#define N_USERS 200000
#define N_ITEMS 400000
#define N_NODES (N_USERS + N_ITEMS)   // 600000
#define EMB_DIM 128
#define N_EDGES 3000000
#define VEC4_PER_ROW (EMB_DIM / 4)    // 32
#define TOTAL_F ((size_t)N_NODES * EMB_DIM)   // 76.8M elems

#define SCAN_BLOCK 1024
#define N_SCAN_BLOCKS ((N_NODES + SCAN_BLOCK - 1) / SCAN_BLOCK)  // 586

// Static scratch (allowed: __device__ globals)
__device__ __half g_bufA[TOTAL_F];     // 153.6 MB
__device__ __half g_bufB[TOTAL_F];     // 153.6 MB
__device__ int    g_count[N_NODES];
__device__ int    g_offset[N_NODES + 1];
__device__ int    g_pos[N_NODES];
__device__ int    g_bsum[SCAN_BLOCK];
__device__ int2   g_pair[N_EDGES];     // (col, val-as-int) packed

// ---------------------------------------------------------------------------
// CSR build
// ---------------------------------------------------------------------------
__global__ void histogram_kernel(const int* __restrict__ rows,
                                 int* __restrict__ count) {
    int e = blockIdx.x * blockDim.x + threadIdx.x;
    if (e < N_EDGES) atomicAdd(&count[rows[e]], 1);
}

__global__ void scan1_kernel(const int* __restrict__ count,
                             int* __restrict__ offset,
                             int* __restrict__ bsum) {
    __shared__ int sh[SCAN_BLOCK];
    int i = blockIdx.x * SCAN_BLOCK + threadIdx.x;
    int v = (i < N_NODES) ? count[i] : 0;
    sh[threadIdx.x] = v;
    __syncthreads();
    #pragma unroll
    for (int d = 1; d < SCAN_BLOCK; d <<= 1) {
        int t = (threadIdx.x >= d) ? sh[threadIdx.x - d] : 0;
        __syncthreads();
        sh[threadIdx.x] += t;
        __syncthreads();
    }
    if (i < N_NODES) offset[i] = sh[threadIdx.x] - v;   // exclusive
    if (threadIdx.x == SCAN_BLOCK - 1) bsum[blockIdx.x] = sh[SCAN_BLOCK - 1];
}

__global__ void scan2_kernel(int* __restrict__ bsum, int nb) {
    __shared__ int sh[SCAN_BLOCK];
    int v = (threadIdx.x < nb) ? bsum[threadIdx.x] : 0;
    sh[threadIdx.x] = v;
    __syncthreads();
    #pragma unroll
    for (int d = 1; d < SCAN_BLOCK; d <<= 1) {
        int t = (threadIdx.x >= d) ? sh[threadIdx.x - d] : 0;
        __syncthreads();
        sh[threadIdx.x] += t;
        __syncthreads();
    }
    if (threadIdx.x < nb) bsum[threadIdx.x] = sh[threadIdx.x] - v;  // exclusive
}

__global__ void scan3_kernel(int* __restrict__ offset,
                             const int* __restrict__ bsum,
                             int* __restrict__ pos) {
    int i = blockIdx.x * SCAN_BLOCK + threadIdx.x;
    if (i < N_NODES) {
        int o = offset[i] + bsum[blockIdx.x];
        offset[i] = o;
        pos[i] = o;
        if (i == N_NODES - 1) offset[N_NODES] = N_EDGES;
    }
}

__global__ void permute_kernel(const int* __restrict__ rows,
                               const int* __restrict__ cols,
                               const float* __restrict__ vals,
                               int* __restrict__ pos,
                               int2* __restrict__ pair) {
    int e = blockIdx.x * blockDim.x + threadIdx.x;
    if (e >= N_EDGES) return;
    int r = rows[e];
    int p = atomicAdd(&pos[r], 1);
    int2 pr;
    pr.x = cols[e];
    pr.y = __float_as_int(vals[e]);
    pair[p] = pr;
}

// ---------------------------------------------------------------------------
// Helpers: fp16 row load (8B per lane) -> float4; float4 -> fp16 store
// ---------------------------------------------------------------------------
__device__ __forceinline__ float4 load_h4(const __half* row, int lane) {
    uint2 raw = __ldg(reinterpret_cast<const uint2*>(row) + lane);
    __half2 h0 = *reinterpret_cast<__half2*>(&raw.x);
    __half2 h1 = *reinterpret_cast<__half2*>(&raw.y);
    float2 f0 = __half22float2(h0);
    float2 f1 = __half22float2(h1);
    return make_float4(f0.x, f0.y, f1.x, f1.y);
}

__device__ __forceinline__ void store_h4(__half* row, int lane, float4 v) {
    __half2 h0 = __floats2half2_rn(v.x, v.y);
    __half2 h1 = __floats2half2_rn(v.z, v.w);
    uint2 raw;
    raw.x = *reinterpret_cast<unsigned*>(&h0);
    raw.y = *reinterpret_cast<unsigned*>(&h1);
    *(reinterpret_cast<uint2*>(row) + lane) = raw;
}

// ---------------------------------------------------------------------------
// Pull-style SpMM: one warp per output row, no atomics, fp32 accumulation.
// SPLIT: gather from split fp32 inputs (layer 1). Else gather fp16 src.
// FUSED: layer-3 epilogue out = 0.25*(x0 + A + B + y), fp32 output.
// ---------------------------------------------------------------------------
template <bool SPLIT, bool FUSED>
__global__ void __launch_bounds__(512)
spmm_kernel(const int* __restrict__ offset,
            const int2* __restrict__ pair,
            const float4* __restrict__ u,     // user embs (v4, fp32)
            const float4* __restrict__ it,    // item embs (v4, fp32)
            const __half* __restrict__ xH,    // gather src (!SPLIT, fp16)
            __half* __restrict__ dstH,        // layer output (fp16)
            const __half* __restrict__ accA,  // FUSED: layer-1 out (fp16)
            const __half* __restrict__ accB,  // FUSED: layer-2 out (fp16)
            float4* __restrict__ out) {       // FUSED: final out (fp32)
    int lane = threadIdx.x & 31;
    int r = (blockIdx.x * blockDim.x + threadIdx.x) >> 5;
    if (r >= N_NODES) return;

    int j = __ldg(offset + r);
    int end = __ldg(offset + r + 1);

    float4 acc0 = make_float4(0.f, 0.f, 0.f, 0.f);
    float4 acc1 = make_float4(0.f, 0.f, 0.f, 0.f);

    #pragma unroll 1
    for (; j + 2 <= end; j += 2) {
        int2 e0 = __ldg(pair + j);
        int2 e1 = __ldg(pair + j + 1);
        float4 m0, m1;
        if (SPLIT) {
            const float4* b0 = (e0.x < N_USERS)
                ? (u + (size_t)e0.x * VEC4_PER_ROW)
                : (it + (size_t)(e0.x - N_USERS) * VEC4_PER_ROW);
            const float4* b1 = (e1.x < N_USERS)
                ? (u + (size_t)e1.x * VEC4_PER_ROW)
                : (it + (size_t)(e1.x - N_USERS) * VEC4_PER_ROW);
            m0 = __ldg(b0 + lane);
            m1 = __ldg(b1 + lane);
        } else {
            m0 = load_h4(xH + (size_t)e0.x * EMB_DIM, lane);
            m1 = load_h4(xH + (size_t)e1.x * EMB_DIM, lane);
        }
        float v0 = __int_as_float(e0.y);
        float v1 = __int_as_float(e1.y);
        acc0.x += v0 * m0.x; acc0.y += v0 * m0.y;
        acc0.z += v0 * m0.z; acc0.w += v0 * m0.w;
        acc1.x += v1 * m1.x; acc1.y += v1 * m1.y;
        acc1.z += v1 * m1.z; acc1.w += v1 * m1.w;
    }
    if (j < end) {
        int2 e0 = __ldg(pair + j);
        float4 m0;
        if (SPLIT) {
            const float4* b0 = (e0.x < N_USERS)
                ? (u + (size_t)e0.x * VEC4_PER_ROW)
                : (it + (size_t)(e0.x - N_USERS) * VEC4_PER_ROW);
            m0 = __ldg(b0 + lane);
        } else {
            m0 = load_h4(xH + (size_t)e0.x * EMB_DIM, lane);
        }
        float v0 = __int_as_float(e0.y);
        acc0.x += v0 * m0.x; acc0.y += v0 * m0.y;
        acc0.z += v0 * m0.z; acc0.w += v0 * m0.w;
    }

    float4 acc;
    acc.x = acc0.x + acc1.x; acc.y = acc0.y + acc1.y;
    acc.z = acc0.z + acc1.z; acc.w = acc0.w + acc1.w;

    if (FUSED) {
        size_t idx = (size_t)r * VEC4_PER_ROW + lane;
        float4 x0 = (r < N_USERS)
                        ? __ldg(u + (size_t)r * VEC4_PER_ROW + lane)
                        : __ldg(it + (size_t)(r - N_USERS) * VEC4_PER_ROW + lane);
        float4 a = load_h4(accA + (size_t)r * EMB_DIM, lane);
        float4 b = load_h4(accB + (size_t)r * EMB_DIM, lane);
        float4 o;
        o.x = 0.25f * (x0.x + a.x + b.x + acc.x);
        o.y = 0.25f * (x0.y + a.y + b.y + acc.y);
        o.z = 0.25f * (x0.z + a.z + b.z + acc.z);
        o.w = 0.25f * (x0.w + a.w + b.w + acc.w);
        out[idx] = o;
    } else {
        store_h4(dstH + (size_t)r * EMB_DIM, lane, acc);
    }
}

extern "C" void kernel_launch(void* const* d_in, const int* in_sizes, int n_in,
                              void* d_out, int out_size) {
    const float4* emb_user = (const float4*)d_in[0];
    const float4* emb_item = (const float4*)d_in[1];
    const int* edge_row = (const int*)d_in[2];
    const int* edge_col = (const int*)d_in[3];
    const float* edge_val = (const float*)d_in[4];
    float4* out = (float4*)d_out;

    __half *A, *B;
    int *count_, *offset_, *pos_, *bsum_;
    int2 *pair_;
    cudaGetSymbolAddress((void**)&A, g_bufA);
    cudaGetSymbolAddress((void**)&B, g_bufB);
    cudaGetSymbolAddress((void**)&count_, g_count);
    cudaGetSymbolAddress((void**)&offset_, g_offset);
    cudaGetSymbolAddress((void**)&pos_, g_pos);
    cudaGetSymbolAddress((void**)&bsum_, g_bsum);
    cudaGetSymbolAddress((void**)&pair_, g_pair);

    const int T = 256;
    const int gridEdge = (N_EDGES + T - 1) / T;
    const int TS = 512;
    const int gridRow = (int)(((size_t)N_NODES * 32 + TS - 1) / TS);

    // ---- CSR build (edges identical across layers: build once) ----
    cudaMemsetAsync(count_, 0, N_NODES * sizeof(int));
    histogram_kernel<<<gridEdge, T>>>(edge_row, count_);
    scan1_kernel<<<N_SCAN_BLOCKS, SCAN_BLOCK>>>(count_, offset_, bsum_);
    scan2_kernel<<<1, SCAN_BLOCK>>>(bsum_, N_SCAN_BLOCKS);
    scan3_kernel<<<N_SCAN_BLOCKS, SCAN_BLOCK>>>(offset_, bsum_, pos_);
    permute_kernel<<<gridEdge, T>>>(edge_row, edge_col, edge_val, pos_, pair_);

    // ---- Layer 1: gather split fp32 inputs -> A (fp16) ----
    spmm_kernel<true, false><<<gridRow, TS>>>(offset_, pair_,
                                              emb_user, emb_item, nullptr,
                                              A, nullptr, nullptr, nullptr);
    // ---- Layer 2: gather A (fp16) -> B (fp16) ----
    spmm_kernel<false, false><<<gridRow, TS>>>(offset_, pair_,
                                               emb_user, emb_item, A,
                                               B, nullptr, nullptr, nullptr);
    // ---- Layer 3 fused: gather B (fp16), out = 0.25*(x0 + A + B + y) ----
    spmm_kernel<false, true><<<gridRow, TS>>>(offset_, pair_,
                                              emb_user, emb_item, B,
                                              nullptr, A, B, out);
}